// round 15
// baseline (speedup 1.0000x reference)
#include <cuda_runtime.h>
#include <cuda_fp16.h>

#define NUSERS 100000
#define NITEMS 50000
#define NN     150000
#define NN_PAD 150016   // multiple of 128
#define EMB    64
#define NE     2000000
#define NB     16384
#define NBLK_SCAN 147   // ceil(NN/1024)

// ---------------- scratch (device globals) ----------------------------------
__device__ __half g_xh[(size_t)NN_PAD * 64];      // input embeddings fp16 (pad rows zero)
__device__ __half g_w1t[256 * 64];                // W1^T: [n=256][k=64] fp16
__device__ __half g_w2t[64 * 256];                // W2^T: [n=64][k=256] fp16
__device__ float  g_w1al[256];                    // per-head W1@a_l
__device__ float  g_w1ar[256];                    // per-head W1@a_r
__device__ __half g_xagg[(size_t)NN_PAD * 256];   // normalized att-agg of x (pad rows BSS-zero)
__device__ float  g_es1[NN * 4];
__device__ float  g_ed1[NN * 4];
__device__ __half g_h2h[(size_t)NN_PAD * 64];     // layer-2 features fp16
__device__ float  g_out2[(size_t)NN * 64];
__device__ float  g_es2[NN];
__device__ float  g_ed2[NN];
// static init = enc(-inf); k_final resets them for the next call
__device__ unsigned g_maxes1_u = 0x007FFFFFu;
__device__ unsigned g_maxed1_u = 0x007FFFFFu;
__device__ unsigned g_maxes2_u = 0x007FFFFFu;
__device__ unsigned g_maxed2_u = 0x007FFFFFu;

// CSR by dst. g_cnt/g_need start BSS-zero; k_final re-zeroes them each call.
__device__ int g_cnt[NN];
__device__ int g_off[NN];
__device__ int g_cur[NN];
__device__ int g_csr_src[NE];
__device__ int g_bsum[NBLK_SCAN];
__device__ unsigned char g_need[NN];              // demand flags for agg2

__device__ __forceinline__ unsigned enc_f(float f) {
    unsigned u = __float_as_uint(f);
    return (u & 0x80000000u) ? ~u : (u | 0x80000000u);
}
__device__ __forceinline__ float dec_f(unsigned u) {
    return (u & 0x80000000u) ? __uint_as_float(u ^ 0x80000000u) : __uint_as_float(~u);
}
__device__ __forceinline__ float lrelu(float v) { return (v > 0.f) ? v : 0.2f * v; }

__device__ __forceinline__ void mma16816(float& d0, float& d1, float& d2, float& d3,
                                         unsigned a0, unsigned a1, unsigned a2, unsigned a3,
                                         unsigned b0, unsigned b1) {
    asm volatile(
        "mma.sync.aligned.m16n8k16.row.col.f32.f16.f16.f32 "
        "{%0,%1,%2,%3},{%4,%5,%6,%7},{%8,%9},{%0,%1,%2,%3};"
        : "+f"(d0), "+f"(d1), "+f"(d2), "+f"(d3)
        : "r"(a0), "r"(a1), "r"(a2), "r"(a3), "r"(b0), "r"(b1));
}
__device__ __forceinline__ unsigned lds_u32(const __half* p) {
    return *reinterpret_cast<const unsigned*>(p);
}

// ---------------- prep: w1a vectors (per-head W1 @ a) -----------------------------
__global__ void k_prep(const float* __restrict__ W1, const float* __restrict__ a1) {
    int t = threadIdx.x;
    int h = t >> 6, k = t & 63;
    float al = 0.f, ar = 0.f;
#pragma unroll
    for (int f = 0; f < 64; f++) {
        float w = W1[k * 256 + h * 64 + f];
        al = fmaf(w, a1[h * 128 + f], al);
        ar = fmaf(w, a1[h * 128 + 64 + f], ar);
    }
    g_w1al[t] = al;
    g_w1ar[t] = ar;
}

// ---------------- mark demanded nodes (races benign) -------------------------------
__global__ void k_mark(const int* __restrict__ uid, const int* __restrict__ iid) {
    int i = blockIdx.x * blockDim.x + threadIdx.x;
    if (i < NB) {
        g_need[uid[i]] = 1;
        g_need[NUSERS + iid[i]] = 1;
    }
}

// ---------------- cvt: x->fp16 + es1/ed1 dots + node maxes + W conversions --------
__global__ void __launch_bounds__(256) k_cvt_fused(
    const float* __restrict__ user, const float* __restrict__ item,
    const float* __restrict__ W1, const float* __restrict__ W2) {
    size_t i0 = (size_t)blockIdx.x * blockDim.x + threadIdx.x;
    size_t stride = (size_t)gridDim.x * blockDim.x;
    for (size_t i = i0; i < 256 * 64; i += stride) {
        int n = (int)(i >> 6), k = (int)(i & 63);
        g_w1t[i] = __float2half(W1[k * 256 + n]);
    }
    for (size_t i = i0; i < 64 * 256; i += stride) {
        int n = (int)(i >> 8), k = (int)(i & 255);
        g_w2t[i] = __float2half(W2[k * 64 + n]);
    }
    int lane = threadIdx.x & 31;
    int gwarp = (int)(i0 >> 5);
    int nwarps = (int)(stride >> 5);
    float2 wl[4], wr[4];
#pragma unroll
    for (int h = 0; h < 4; h++) {
        wl[h] = *reinterpret_cast<const float2*>(&g_w1al[h * 64 + lane * 2]);
        wr[h] = *reinterpret_cast<const float2*>(&g_w1ar[h * 64 + lane * 2]);
    }
    float mxe = -3.4e38f, mxd = -3.4e38f;
    for (int row = gwarp; row < NN_PAD; row += nwarps) {
        float2 xv = make_float2(0.f, 0.f);
        if (row < NUSERS)
            xv = *reinterpret_cast<const float2*>(&user[(size_t)row * 64 + lane * 2]);
        else if (row < NN)
            xv = *reinterpret_cast<const float2*>(&item[(size_t)(row - NUSERS) * 64 + lane * 2]);
        *reinterpret_cast<__half2*>(&g_xh[(size_t)row * 64 + lane * 2]) =
            __floats2half2_rn(xv.x, xv.y);
        if (row < NN) {
            float e[8];
#pragma unroll
            for (int h = 0; h < 4; h++) {
                e[h]     = fmaf(xv.x, wl[h].x, xv.y * wl[h].y);
                e[4 + h] = fmaf(xv.x, wr[h].x, xv.y * wr[h].y);
            }
#pragma unroll
            for (int o = 16; o > 0; o >>= 1)
#pragma unroll
                for (int q = 0; q < 8; q++)
                    e[q] += __shfl_down_sync(0xffffffffu, e[q], o);
            if (lane == 0) {
                *reinterpret_cast<float4*>(&g_es1[row * 4]) =
                    make_float4(e[0], e[1], e[2], e[3]);
                *reinterpret_cast<float4*>(&g_ed1[row * 4]) =
                    make_float4(e[4], e[5], e[6], e[7]);
                mxe = fmaxf(mxe, fmaxf(fmaxf(e[0], e[1]), fmaxf(e[2], e[3])));
                mxd = fmaxf(mxd, fmaxf(fmaxf(e[4], e[5]), fmaxf(e[6], e[7])));
            }
        }
    }
    if (lane == 0 && mxe > -3.3e38f) {
        atomicMax(&g_maxes1_u, enc_f(mxe));
        atomicMax(&g_maxed1_u, enc_f(mxd));
    }
}

// ---------------- CSR build (chain B) ----------------------------------------------
__global__ void k_hist(const int* __restrict__ ei) {
    for (int e = blockIdx.x * 256 + threadIdx.x; e < NE; e += gridDim.x * 256)
        atomicAdd(&g_cnt[ei[NE + e]], 1);
}

__global__ void __launch_bounds__(1024) k_scan_block() {
    __shared__ int sh[1024];
    int t = threadIdx.x;
    int i = blockIdx.x * 1024 + t;
    int v = (i < NN) ? g_cnt[i] : 0;
    sh[t] = v;
    __syncthreads();
#pragma unroll
    for (int o = 1; o < 1024; o <<= 1) {
        int x = (t >= o) ? sh[t - o] : 0;
        __syncthreads();
        sh[t] += x;
        __syncthreads();
    }
    if (i < NN) g_off[i] = sh[t] - v;
    if (t == 1023) g_bsum[blockIdx.x] = sh[1023];
}

__global__ void __launch_bounds__(1024) k_scan_fin() {
    __shared__ int base_sh;
    int b = blockIdx.x, t = threadIdx.x;
    if (t < 32) {
        int v = 0;
        for (int i = t; i < b; i += 32) v += g_bsum[i];
#pragma unroll
        for (int o = 16; o > 0; o >>= 1) v += __shfl_down_sync(0xffffffffu, v, o);
        if (t == 0) base_sh = v;
    }
    __syncthreads();
    int i = b * 1024 + t;
    if (i < NN) {
        int o = g_off[i] + base_sh;
        g_off[i] = o;
        g_cur[i] = o;
    }
}

__global__ void k_scatter(const int* __restrict__ ei) {
    int e = blockIdx.x * 256 + threadIdx.x;
    if (e >= NE) return;
    int d = ei[NE + e];
    int pos = atomicAdd(&g_cur[d], 1);
    g_csr_src[pos] = ei[e];
}

// ---------------- layer-1 aggregation: software-pipelined groups -------------------
__global__ void __launch_bounds__(256) k_agg1() {
    int gw = (blockIdx.x * 256 + threadIdx.x) >> 5;
    int lane = threadIdx.x & 31;
    if (gw >= NN) return;
    int d = gw;
    int n0 = g_off[d];
    int cnt = g_cnt[d];
    float M = lrelu(dec_f(g_maxes1_u) + dec_f(g_maxed1_u));
    float acc[8] = {0.f, 0.f, 0.f, 0.f, 0.f, 0.f, 0.f, 0.f};
    float ss = 0.f;
    int myh = lane >> 3;
    int xofs = (lane & 7) * 8;
    float ed_l = g_ed1[d * 4 + myh];
    int j = n0, end = n0 + cnt;

    // single-edge body (peel + tail)
#define AGG1_ONE(SRC)                                                                  \
    {                                                                                  \
        int s_ = (SRC);                                                                \
        float4 r_ = __ldcg(reinterpret_cast<const float4*>(&g_xh[(size_t)s_ * 64 + xofs])); \
        float w_ = __expf(lrelu(g_es1[s_ * 4 + myh] + ed_l) - M);                      \
        ss += w_;                                                                      \
        const __half2* h_ = reinterpret_cast<const __half2*>(&r_);                     \
        _Pragma("unroll")                                                              \
        for (int q = 0; q < 4; q++) {                                                  \
            float2 f_ = __half22float2(h_[q]);                                         \
            acc[2 * q]     = fmaf(w_, f_.x, acc[2 * q]);                               \
            acc[2 * q + 1] = fmaf(w_, f_.y, acc[2 * q + 1]);                           \
        }                                                                              \
    }

    // load stage: issue all memory ops for a 4-edge group (no exp, no fma)
#define AGG1_LOAD(S4, R, E)                                                            \
    {                                                                                  \
        R[0] = __ldcg(reinterpret_cast<const float4*>(&g_xh[(size_t)(S4).x * 64 + xofs])); \
        R[1] = __ldcg(reinterpret_cast<const float4*>(&g_xh[(size_t)(S4).y * 64 + xofs])); \
        R[2] = __ldcg(reinterpret_cast<const float4*>(&g_xh[(size_t)(S4).z * 64 + xofs])); \
        R[3] = __ldcg(reinterpret_cast<const float4*>(&g_xh[(size_t)(S4).w * 64 + xofs])); \
        E[0] = g_es1[(S4).x * 4 + myh];                                                \
        E[1] = g_es1[(S4).y * 4 + myh];                                                \
        E[2] = g_es1[(S4).z * 4 + myh];                                                \
        E[3] = g_es1[(S4).w * 4 + myh];                                                \
    }

    // consume stage: exp + fma on a loaded group
#define AGG1_CONS(R, E)                                                                \
    {                                                                                  \
        float w0_ = __expf(lrelu(E[0] + ed_l) - M);                                    \
        float w1_ = __expf(lrelu(E[1] + ed_l) - M);                                    \
        float w2_ = __expf(lrelu(E[2] + ed_l) - M);                                    \
        float w3_ = __expf(lrelu(E[3] + ed_l) - M);                                    \
        ss += (w0_ + w1_) + (w2_ + w3_);                                               \
        const __half2* h0_ = reinterpret_cast<const __half2*>(&R[0]);                  \
        const __half2* h1_ = reinterpret_cast<const __half2*>(&R[1]);                  \
        const __half2* h2_ = reinterpret_cast<const __half2*>(&R[2]);                  \
        const __half2* h3_ = reinterpret_cast<const __half2*>(&R[3]);                  \
        _Pragma("unroll")                                                              \
        for (int q = 0; q < 4; q++) {                                                  \
            float2 f0_ = __half22float2(h0_[q]);                                       \
            float2 f1_ = __half22float2(h1_[q]);                                       \
            float2 f2_ = __half22float2(h2_[q]);                                       \
            float2 f3_ = __half22float2(h3_[q]);                                       \
            acc[2 * q]     = fmaf(w0_, f0_.x, fmaf(w1_, f1_.x, fmaf(w2_, f2_.x, fmaf(w3_, f3_.x, acc[2 * q])))); \
            acc[2 * q + 1] = fmaf(w0_, f0_.y, fmaf(w1_, f1_.y, fmaf(w2_, f2_.y, fmaf(w3_, f3_.y, acc[2 * q + 1])))); \
        }                                                                              \
    }

    for (; j < end && (j & 3); j++) AGG1_ONE(g_csr_src[j]);
    int nfull = (end - j) >> 2;
    if (nfull > 0) {
        float4 rA[4]; float eA[4];
        float4 rB[4]; float eB[4];
        int4 s4 = *reinterpret_cast<const int4*>(&g_csr_src[j]);
        AGG1_LOAD(s4, rA, eA);
        for (int gi = 1; gi < nfull; gi++) {
            int4 s4n = *reinterpret_cast<const int4*>(&g_csr_src[j + gi * 4]);
            AGG1_LOAD(s4n, rB, eB);        // next group's loads in flight...
            AGG1_CONS(rA, eA);             // ...while consuming current group
#pragma unroll
            for (int q = 0; q < 4; q++) { rA[q] = rB[q]; eA[q] = eB[q]; }
        }
        AGG1_CONS(rA, eA);
        j += nfull * 4;
    }
    for (; j < end; j++) AGG1_ONE(g_csr_src[j]);
#undef AGG1_ONE
#undef AGG1_LOAD
#undef AGG1_CONS

    float inv = 1.f / (ss + 1e-8f);
    union { uint4 u; __half2 h2[4]; } pk;
#pragma unroll
    for (int q = 0; q < 4; q++)
        pk.h2[q] = __floats2half2_rn(acc[2 * q] * inv, acc[2 * q + 1] * inv);
    __stcs(reinterpret_cast<uint4*>(&g_xagg[(size_t)d * 256 + lane * 8]), pk.u);
}

// ---------------- fused GEMM1b+GEMM2: h2 = elu(xagg@blockdiagW1)@W2, + es2/ed2 -----
__global__ void __launch_bounds__(256) k_gemm12_mma(const float* __restrict__ a2) {
    extern __shared__ __half sm[];
    __half* Bt1 = sm;                       // [256][72]
    __half* Bt2 = Bt1 + 256 * 72;           // [64][264]
    __half* As  = Bt2 + 64 * 264;           // [32][264]
    __half* O   = As + 32 * 264;            // [32][264]
    float* part_es = reinterpret_cast<float*>(O + 32 * 264);  // [4][32]
    float* part_ed = part_es + 128;

    int t = threadIdx.x;
    int lane = t & 31, wid = t >> 5;
    int g = lane >> 2, tg = lane & 3;

#pragma unroll
    for (int i = 0; i < 8; i++) {
        int u = t + i * 256;
        int r = u >> 3, c = (u & 7) * 8;
        *reinterpret_cast<uint4*>(&Bt1[r * 72 + c]) =
            *reinterpret_cast<const uint4*>(&g_w1t[r * 64 + c]);
    }
#pragma unroll
    for (int i = 0; i < 8; i++) {
        int u = t + i * 256;
        int r = u >> 5, c = (u & 31) * 8;
        *reinterpret_cast<uint4*>(&Bt2[r * 264 + c]) =
            *reinterpret_cast<const uint4*>(&g_w2t[r * 256 + c]);
    }

    int wm = (wid & 1) * 16;
    int wn1 = (wid >> 1) * 64;
    int akofs = (wid >> 1) * 64;
    int wn2 = (wid >> 1) * 16;
    float a2l2[2][2], a2r2[2][2];
#pragma unroll
    for (int ns = 0; ns < 2; ns++)
#pragma unroll
        for (int c = 0; c < 2; c++) {
            int col = wn2 + ns * 8 + 2 * tg + c;
            a2l2[ns][c] = a2[col];
            a2r2[ns][c] = a2[64 + col];
        }

    float mx_es = -3.4e38f, mx_ed = -3.4e38f;
    const int NT = NN_PAD / 32;
    for (int tile = blockIdx.x; tile < NT; tile += gridDim.x) {
        __syncthreads();
#pragma unroll
        for (int i = 0; i < 4; i++) {
            int u = t + i * 256;
            int r = u >> 5, c = (u & 31) * 8;
            *reinterpret_cast<uint4*>(&As[r * 264 + c]) =
                *reinterpret_cast<const uint4*>(&g_xagg[(size_t)(tile * 32 + r) * 256 + c]);
        }
        __syncthreads();

        float acc[8][4];
#pragma unroll
        for (int ns = 0; ns < 8; ns++)
#pragma unroll
            for (int q = 0; q < 4; q++) acc[ns][q] = 0.f;
#pragma unroll
        for (int kt = 0; kt < 4; kt++) {
            int kbA = akofs + kt * 16 + 2 * tg;
            int kbB = kt * 16 + 2 * tg;
            unsigned a0 = lds_u32(&As[(wm + g) * 264 + kbA]);
            unsigned a1f = lds_u32(&As[(wm + g + 8) * 264 + kbA]);
            unsigned a2f = lds_u32(&As[(wm + g) * 264 + kbA + 8]);
            unsigned a3f = lds_u32(&As[(wm + g + 8) * 264 + kbA + 8]);
#pragma unroll
            for (int ns = 0; ns < 8; ns++) {
                unsigned b0 = lds_u32(&Bt1[(wn1 + ns * 8 + g) * 72 + kbB]);
                unsigned b1 = lds_u32(&Bt1[(wn1 + ns * 8 + g) * 72 + kbB + 8]);
                mma16816(acc[ns][0], acc[ns][1], acc[ns][2], acc[ns][3],
                         a0, a1f, a2f, a3f, b0, b1);
            }
        }
#pragma unroll
        for (int ns = 0; ns < 8; ns++) {
            int col = wn1 + ns * 8 + 2 * tg;
#pragma unroll
            for (int q = 0; q < 4; q++)
                acc[ns][q] = (acc[ns][q] > 0.f) ? acc[ns][q] : expm1f(acc[ns][q]);
            *reinterpret_cast<__half2*>(&O[(wm + g) * 264 + col]) =
                __floats2half2_rn(acc[ns][0], acc[ns][1]);
            *reinterpret_cast<__half2*>(&O[(wm + g + 8) * 264 + col]) =
                __floats2half2_rn(acc[ns][2], acc[ns][3]);
        }
        __syncthreads();

        float acc2[2][4];
#pragma unroll
        for (int ns = 0; ns < 2; ns++)
#pragma unroll
            for (int q = 0; q < 4; q++) acc2[ns][q] = 0.f;
#pragma unroll
        for (int kt = 0; kt < 16; kt++) {
            int kb = kt * 16 + 2 * tg;
            unsigned a0 = lds_u32(&O[(wm + g) * 264 + kb]);
            unsigned a1f = lds_u32(&O[(wm + g + 8) * 264 + kb]);
            unsigned a2f = lds_u32(&O[(wm + g) * 264 + kb + 8]);
            unsigned a3f = lds_u32(&O[(wm + g + 8) * 264 + kb + 8]);
#pragma unroll
            for (int ns = 0; ns < 2; ns++) {
                unsigned b0 = lds_u32(&Bt2[(wn2 + ns * 8 + g) * 264 + kb]);
                unsigned b1 = lds_u32(&Bt2[(wn2 + ns * 8 + g) * 264 + kb + 8]);
                mma16816(acc2[ns][0], acc2[ns][1], acc2[ns][2], acc2[ns][3],
                         a0, a1f, a2f, a3f, b0, b1);
            }
        }
        int row0 = tile * 32 + wm + g;
#pragma unroll
        for (int ns = 0; ns < 2; ns++) {
            int col = wn2 + ns * 8 + 2 * tg;
            if (row0 < NN)
                *reinterpret_cast<__half2*>(&g_h2h[(size_t)row0 * 64 + col]) =
                    __floats2half2_rn(acc2[ns][0], acc2[ns][1]);
            if (row0 + 8 < NN)
                *reinterpret_cast<__half2*>(&g_h2h[(size_t)(row0 + 8) * 64 + col]) =
                    __floats2half2_rn(acc2[ns][2], acc2[ns][3]);
        }
        float es0 = 0.f, ed0 = 0.f, es8 = 0.f, ed8 = 0.f;
#pragma unroll
        for (int ns = 0; ns < 2; ns++) {
            es0 = fmaf(acc2[ns][0], a2l2[ns][0], fmaf(acc2[ns][1], a2l2[ns][1], es0));
            ed0 = fmaf(acc2[ns][0], a2r2[ns][0], fmaf(acc2[ns][1], a2r2[ns][1], ed0));
            es8 = fmaf(acc2[ns][2], a2l2[ns][0], fmaf(acc2[ns][3], a2l2[ns][1], es8));
            ed8 = fmaf(acc2[ns][2], a2r2[ns][0], fmaf(acc2[ns][3], a2r2[ns][1], ed8));
        }
#pragma unroll
        for (int o = 1; o < 4; o <<= 1) {
            es0 += __shfl_xor_sync(0xffffffffu, es0, o);
            ed0 += __shfl_xor_sync(0xffffffffu, ed0, o);
            es8 += __shfl_xor_sync(0xffffffffu, es8, o);
            ed8 += __shfl_xor_sync(0xffffffffu, ed8, o);
        }
        if (tg == 0) {
            int cg = wid >> 1;
            part_es[cg * 32 + wm + g] = es0;
            part_es[cg * 32 + wm + g + 8] = es8;
            part_ed[cg * 32 + wm + g] = ed0;
            part_ed[cg * 32 + wm + g + 8] = ed8;
        }
        __syncthreads();
        if (t < 32) {
            int row = tile * 32 + t;
            float es = part_es[t] + part_es[32 + t] + part_es[64 + t] + part_es[96 + t];
            float ed = part_ed[t] + part_ed[32 + t] + part_ed[64 + t] + part_ed[96 + t];
            if (row < NN) {
                g_es2[row] = es;
                g_ed2[row] = ed;
                mx_es = fmaxf(mx_es, es);
                mx_ed = fmaxf(mx_ed, ed);
            }
        }
    }
    if (t < 32 && mx_es > -3.3e38f) {
        atomicMax(&g_maxes2_u, enc_f(mx_es));
        atomicMax(&g_maxed2_u, enc_f(mx_ed));
    }
}

// ---------------- layer-2 aggregation: warp/dst, demand-pruned ---------------------
__global__ void __launch_bounds__(256) k_agg2(
    const float* __restrict__ user, const float* __restrict__ item) {
    int gw = (blockIdx.x * 256 + threadIdx.x) >> 5;
    int lane = threadIdx.x & 31;
    if (gw >= NN) return;
    int d = gw;
    if (!g_need[d]) return;
    int n0 = g_off[d];
    int cnt = g_cnt[d];
    float M = lrelu(dec_f(g_maxes2_u) + dec_f(g_maxed2_u));
    float2 acc = make_float2(0.f, 0.f);
    float ss = 0.f;
    float ed_d = g_ed2[d];
    int j = n0, end = n0 + cnt;
    for (; j + 3 < end; j += 4) {
        int s0 = g_csr_src[j], s1 = g_csr_src[j + 1];
        int s2 = g_csr_src[j + 2], s3 = g_csr_src[j + 3];
        __half2 hr0 = __ldcg(reinterpret_cast<const __half2*>(&g_h2h[(size_t)s0 * 64 + lane * 2]));
        __half2 hr1 = __ldcg(reinterpret_cast<const __half2*>(&g_h2h[(size_t)s1 * 64 + lane * 2]));
        __half2 hr2 = __ldcg(reinterpret_cast<const __half2*>(&g_h2h[(size_t)s2 * 64 + lane * 2]));
        __half2 hr3 = __ldcg(reinterpret_cast<const __half2*>(&g_h2h[(size_t)s3 * 64 + lane * 2]));
        float w0 = __expf(lrelu(g_es2[s0] + ed_d) - M);
        float w1 = __expf(lrelu(g_es2[s1] + ed_d) - M);
        float w2 = __expf(lrelu(g_es2[s2] + ed_d) - M);
        float w3 = __expf(lrelu(g_es2[s3] + ed_d) - M);
        ss += (w0 + w1) + (w2 + w3);
        float2 f0 = __half22float2(hr0);
        float2 f1 = __half22float2(hr1);
        float2 f2 = __half22float2(hr2);
        float2 f3 = __half22float2(hr3);
        acc.x = fmaf(w0, f0.x, fmaf(w1, f1.x, fmaf(w2, f2.x, fmaf(w3, f3.x, acc.x))));
        acc.y = fmaf(w0, f0.y, fmaf(w1, f1.y, fmaf(w2, f2.y, fmaf(w3, f3.y, acc.y))));
    }
    for (; j < end; j++) {
        int s0 = g_csr_src[j];
        __half2 hr0 = __ldcg(reinterpret_cast<const __half2*>(&g_h2h[(size_t)s0 * 64 + lane * 2]));
        float w0 = __expf(lrelu(g_es2[s0] + ed_d) - M);
        ss += w0;
        float2 f0 = __half22float2(hr0);
        acc.x = fmaf(w0, f0.x, acc.x);
        acc.y = fmaf(w0, f0.y, acc.y);
    }
    float inv = 1.f / (ss + 1e-8f);
    float2 emb = (d < NUSERS)
        ? *reinterpret_cast<const float2*>(&user[(size_t)d * 64 + lane * 2])
        : *reinterpret_cast<const float2*>(&item[(size_t)(d - NUSERS) * 64 + lane * 2]);
    float2 out = make_float2(acc.x * inv + emb.x, acc.y * inv + emb.y);
    *reinterpret_cast<float2*>(&g_out2[(size_t)d * 64 + lane * 2]) = out;
}

// ---------------- final scoring + state reset for next call ------------------------
__global__ void k_final(const int* __restrict__ uid, const int* __restrict__ iid,
                        float* __restrict__ out) {
    int tid = blockIdx.x * blockDim.x + threadIdx.x;
    if (tid < NN) { g_cnt[tid] = 0; g_need[tid] = 0; }
    if (tid == 0) {
        g_maxes1_u = 0x007FFFFFu; g_maxed1_u = 0x007FFFFFu;
        g_maxes2_u = 0x007FFFFFu; g_maxed2_u = 0x007FFFFFu;
    }
    int gw = tid >> 5;
    int lane = threadIdx.x & 31;
    if (gw >= NB) return;
    int u = uid[gw];
    int it = NUSERS + iid[gw];
    float p = 0.f;
#pragma unroll
    for (int i = 0; i < 2; i++) {
        int f = i * 32 + lane;
        p += g_out2[(size_t)u * 64 + f] * g_out2[(size_t)it * 64 + f];
    }
#pragma unroll
    for (int o = 16; o > 0; o >>= 1) p += __shfl_down_sync(0xffffffffu, p, o);
    if (lane == 0) out[gw] = p;
}

// ---------------- launch -------------------------------------------------------------
#define GEMM12_SMEM (256*72*2 + 64*264*2 + 32*264*2 + 32*264*2 + 256*4)

extern "C" void kernel_launch(void* const* d_in, const int* in_sizes, int n_in,
                              void* d_out, int out_size) {
    const float* user = (const float*)d_in[0];
    const float* item = (const float*)d_in[1];
    const float* W1 = (const float*)d_in[2];
    const float* a1 = (const float*)d_in[3];
    const float* W2 = (const float*)d_in[4];
    const float* a2 = (const float*)d_in[5];
    const int* ei = (const int*)d_in[6];
    const int* uid = (const int*)d_in[7];
    const int* iid = (const int*)d_in[8];
    float* out = (float*)d_out;

    static cudaStream_t s2 = nullptr;
    static cudaEvent_t evFork = nullptr, evJoin = nullptr;
    if (s2 == nullptr) {
        cudaStreamCreateWithFlags(&s2, cudaStreamNonBlocking);
        cudaEventCreateWithFlags(&evFork, cudaEventDisableTiming);
        cudaEventCreateWithFlags(&evJoin, cudaEventDisableTiming);
        cudaFuncSetAttribute(k_gemm12_mma,
                             cudaFuncAttributeMaxDynamicSharedMemorySize, GEMM12_SMEM);
    }

    // fork: chain B (CSR build) on s2
    cudaEventRecord(evFork, 0);
    cudaStreamWaitEvent(s2, evFork, 0);
    k_hist<<<2048, 256, 0, s2>>>(ei);
    k_scan_block<<<NBLK_SCAN, 1024, 0, s2>>>();
    k_scan_fin<<<NBLK_SCAN, 1024, 0, s2>>>();
    k_scatter<<<(NE + 255) / 256, 256, 0, s2>>>(ei);
    cudaEventRecord(evJoin, s2);

    // chain A: w1a prep, demand marks, then fused convert + es1/ed1
    k_prep<<<1, 256>>>(W1, a1);
    k_mark<<<(NB + 255) / 256, 256>>>(uid, iid);
    k_cvt_fused<<<2048, 256>>>(user, item, W1, W2);

    // join, then serial tail
    cudaStreamWaitEvent(0, evJoin, 0);
    k_agg1<<<(NN * 32 + 255) / 256, 256>>>();
    k_gemm12_mma<<<296, 256, GEMM12_SMEM>>>(a2);
    k_agg2<<<(NN * 32 + 255) / 256, 256>>>(user, item);
    k_final<<<NB * 32 / 256, 256>>>(uid, iid, out);
}

// round 16
// speedup vs baseline: 1.2099x; 1.2099x over previous
#include <cuda_runtime.h>
#include <cuda_fp16.h>

#define NUSERS 100000
#define NITEMS 50000
#define NN     150000
#define NN_PAD 150016   // multiple of 128
#define EMB    64
#define NE     2000000
#define NB     16384
#define NBLK_SCAN 147   // ceil(NN/1024)

// ---------------- scratch (device globals) ----------------------------------
__device__ __half g_xh[(size_t)NN_PAD * 64];      // input embeddings fp16 (pad rows zero)
__device__ __half g_w1t[256 * 64];                // W1^T: [n=256][k=64] fp16
__device__ __half g_w2t[64 * 256];                // W2^T: [n=64][k=256] fp16
__device__ float  g_w1al[256];                    // per-head W1@a_l
__device__ float  g_w1ar[256];                    // per-head W1@a_r
__device__ __half g_xagg[(size_t)NN_PAD * 256];   // normalized att-agg of x (pad rows BSS-zero)
__device__ float  g_es1[NN * 4];
__device__ float  g_ed1[NN * 4];
__device__ __half g_h2h[(size_t)NN_PAD * 64];     // layer-2 features fp16
__device__ float  g_out2[(size_t)NN * 64];
__device__ float  g_es2[NN];
__device__ float  g_ed2[NN];
// static init = enc(-inf); k_final resets them for the next call
__device__ unsigned g_maxes1_u = 0x007FFFFFu;
__device__ unsigned g_maxed1_u = 0x007FFFFFu;
__device__ unsigned g_maxes2_u = 0x007FFFFFu;
__device__ unsigned g_maxed2_u = 0x007FFFFFu;

// CSR by dst. g_cnt/g_need start BSS-zero; k_final re-zeroes them each call.
__device__ int g_cnt[NN];
__device__ int g_off[NN];
__device__ int g_cur[NN];
__device__ int g_csr_src[NE];
__device__ int g_bsum[NBLK_SCAN];
__device__ unsigned char g_need[NN];              // demand flags for agg2

__device__ __forceinline__ unsigned enc_f(float f) {
    unsigned u = __float_as_uint(f);
    return (u & 0x80000000u) ? ~u : (u | 0x80000000u);
}
__device__ __forceinline__ float dec_f(unsigned u) {
    return (u & 0x80000000u) ? __uint_as_float(u ^ 0x80000000u) : __uint_as_float(~u);
}
__device__ __forceinline__ float lrelu(float v) { return (v > 0.f) ? v : 0.2f * v; }

__device__ __forceinline__ void mma16816(float& d0, float& d1, float& d2, float& d3,
                                         unsigned a0, unsigned a1, unsigned a2, unsigned a3,
                                         unsigned b0, unsigned b1) {
    asm volatile(
        "mma.sync.aligned.m16n8k16.row.col.f32.f16.f16.f32 "
        "{%0,%1,%2,%3},{%4,%5,%6,%7},{%8,%9},{%0,%1,%2,%3};"
        : "+f"(d0), "+f"(d1), "+f"(d2), "+f"(d3)
        : "r"(a0), "r"(a1), "r"(a2), "r"(a3), "r"(b0), "r"(b1));
}
__device__ __forceinline__ unsigned lds_u32(const __half* p) {
    return *reinterpret_cast<const unsigned*>(p);
}

// ---------------- prep + mark: block 0 computes w1a; blocks 1.. mark demand --------
__global__ void k_prep_mark(const float* __restrict__ W1, const float* __restrict__ a1,
                            const int* __restrict__ uid, const int* __restrict__ iid) {
    if (blockIdx.x == 0) {
        int t = threadIdx.x;
        int h = t >> 6, k = t & 63;
        float al = 0.f, ar = 0.f;
#pragma unroll
        for (int f = 0; f < 64; f++) {
            float w = W1[k * 256 + h * 64 + f];
            al = fmaf(w, a1[h * 128 + f], al);
            ar = fmaf(w, a1[h * 128 + 64 + f], ar);
        }
        g_w1al[t] = al;
        g_w1ar[t] = ar;
    } else {
        int i = (blockIdx.x - 1) * blockDim.x + threadIdx.x;
        if (i < NB) {
            g_need[uid[i]] = 1;
            g_need[NUSERS + iid[i]] = 1;
        }
    }
}

// ---------------- cvt: x->fp16 + es1/ed1 dots + node maxes + W conversions --------
__global__ void __launch_bounds__(256) k_cvt_fused(
    const float* __restrict__ user, const float* __restrict__ item,
    const float* __restrict__ W1, const float* __restrict__ W2) {
    size_t i0 = (size_t)blockIdx.x * blockDim.x + threadIdx.x;
    size_t stride = (size_t)gridDim.x * blockDim.x;
    for (size_t i = i0; i < 256 * 64; i += stride) {
        int n = (int)(i >> 6), k = (int)(i & 63);
        g_w1t[i] = __float2half(W1[k * 256 + n]);
    }
    for (size_t i = i0; i < 64 * 256; i += stride) {
        int n = (int)(i >> 8), k = (int)(i & 255);
        g_w2t[i] = __float2half(W2[k * 64 + n]);
    }
    int lane = threadIdx.x & 31;
    int gwarp = (int)(i0 >> 5);
    int nwarps = (int)(stride >> 5);
    float2 wl[4], wr[4];
#pragma unroll
    for (int h = 0; h < 4; h++) {
        wl[h] = *reinterpret_cast<const float2*>(&g_w1al[h * 64 + lane * 2]);
        wr[h] = *reinterpret_cast<const float2*>(&g_w1ar[h * 64 + lane * 2]);
    }
    float mxe = -3.4e38f, mxd = -3.4e38f;
    for (int row = gwarp; row < NN_PAD; row += nwarps) {
        float2 xv = make_float2(0.f, 0.f);
        if (row < NUSERS)
            xv = *reinterpret_cast<const float2*>(&user[(size_t)row * 64 + lane * 2]);
        else if (row < NN)
            xv = *reinterpret_cast<const float2*>(&item[(size_t)(row - NUSERS) * 64 + lane * 2]);
        *reinterpret_cast<__half2*>(&g_xh[(size_t)row * 64 + lane * 2]) =
            __floats2half2_rn(xv.x, xv.y);
        if (row < NN) {
            float e[8];
#pragma unroll
            for (int h = 0; h < 4; h++) {
                e[h]     = fmaf(xv.x, wl[h].x, xv.y * wl[h].y);
                e[4 + h] = fmaf(xv.x, wr[h].x, xv.y * wr[h].y);
            }
#pragma unroll
            for (int o = 16; o > 0; o >>= 1)
#pragma unroll
                for (int q = 0; q < 8; q++)
                    e[q] += __shfl_down_sync(0xffffffffu, e[q], o);
            if (lane == 0) {
                *reinterpret_cast<float4*>(&g_es1[row * 4]) =
                    make_float4(e[0], e[1], e[2], e[3]);
                *reinterpret_cast<float4*>(&g_ed1[row * 4]) =
                    make_float4(e[4], e[5], e[6], e[7]);
                mxe = fmaxf(mxe, fmaxf(fmaxf(e[0], e[1]), fmaxf(e[2], e[3])));
                mxd = fmaxf(mxd, fmaxf(fmaxf(e[4], e[5]), fmaxf(e[6], e[7])));
            }
        }
    }
    if (lane == 0 && mxe > -3.3e38f) {
        atomicMax(&g_maxes1_u, enc_f(mxe));
        atomicMax(&g_maxed1_u, enc_f(mxd));
    }
}

// ---------------- CSR build (chain B) ----------------------------------------------
__global__ void k_hist(const int* __restrict__ ei) {
    for (int e = blockIdx.x * 256 + threadIdx.x; e < NE; e += gridDim.x * 256)
        atomicAdd(&g_cnt[ei[NE + e]], 1);
}

__global__ void __launch_bounds__(1024) k_scan_block() {
    __shared__ int sh[1024];
    int t = threadIdx.x;
    int i = blockIdx.x * 1024 + t;
    int v = (i < NN) ? g_cnt[i] : 0;
    sh[t] = v;
    __syncthreads();
#pragma unroll
    for (int o = 1; o < 1024; o <<= 1) {
        int x = (t >= o) ? sh[t - o] : 0;
        __syncthreads();
        sh[t] += x;
        __syncthreads();
    }
    if (i < NN) g_off[i] = sh[t] - v;
    if (t == 1023) g_bsum[blockIdx.x] = sh[1023];
}

__global__ void __launch_bounds__(1024) k_scan_fin() {
    __shared__ int base_sh;
    int b = blockIdx.x, t = threadIdx.x;
    if (t < 32) {
        int v = 0;
        for (int i = t; i < b; i += 32) v += g_bsum[i];
#pragma unroll
        for (int o = 16; o > 0; o >>= 1) v += __shfl_down_sync(0xffffffffu, v, o);
        if (t == 0) base_sh = v;
    }
    __syncthreads();
    int i = b * 1024 + t;
    if (i < NN) {
        int o = g_off[i] + base_sh;
        g_off[i] = o;
        g_cur[i] = o;
    }
}

__global__ void k_scatter(const int* __restrict__ ei) {
    int e = blockIdx.x * 256 + threadIdx.x;
    if (e >= NE) return;
    int d = ei[NE + e];
    int pos = atomicAdd(&g_cur[d], 1);
    g_csr_src[pos] = ei[e];
}

// ---------------- layer-1 aggregation over x rows (R14 winner, exact) --------------
__global__ void __launch_bounds__(256) k_agg1() {
    int gw = (blockIdx.x * 256 + threadIdx.x) >> 5;
    int lane = threadIdx.x & 31;
    if (gw >= NN) return;
    int d = gw;
    int n0 = g_off[d];
    int cnt = g_cnt[d];
    float M = lrelu(dec_f(g_maxes1_u) + dec_f(g_maxed1_u));
    float acc[8] = {0.f, 0.f, 0.f, 0.f, 0.f, 0.f, 0.f, 0.f};
    float ss = 0.f;
    int myh = lane >> 3;
    int xofs = (lane & 7) * 8;
    float ed_l = g_ed1[d * 4 + myh];
    int j = n0, end = n0 + cnt;

#define AGG1_ONE(SRC)                                                                  \
    {                                                                                  \
        int s_ = (SRC);                                                                \
        float4 r_ = __ldcg(reinterpret_cast<const float4*>(&g_xh[(size_t)s_ * 64 + xofs])); \
        float w_ = __expf(lrelu(g_es1[s_ * 4 + myh] + ed_l) - M);                      \
        ss += w_;                                                                      \
        const __half2* h_ = reinterpret_cast<const __half2*>(&r_);                     \
        _Pragma("unroll")                                                              \
        for (int q = 0; q < 4; q++) {                                                  \
            float2 f_ = __half22float2(h_[q]);                                         \
            acc[2 * q]     = fmaf(w_, f_.x, acc[2 * q]);                               \
            acc[2 * q + 1] = fmaf(w_, f_.y, acc[2 * q + 1]);                           \
        }                                                                              \
    }

    for (; j < end && (j & 3); j++) AGG1_ONE(g_csr_src[j]);
    for (; j + 3 < end; j += 4) {
        int4 s4 = *reinterpret_cast<const int4*>(&g_csr_src[j]);
        float4 r0 = __ldcg(reinterpret_cast<const float4*>(&g_xh[(size_t)s4.x * 64 + xofs]));
        float4 r1 = __ldcg(reinterpret_cast<const float4*>(&g_xh[(size_t)s4.y * 64 + xofs]));
        float4 r2 = __ldcg(reinterpret_cast<const float4*>(&g_xh[(size_t)s4.z * 64 + xofs]));
        float4 r3 = __ldcg(reinterpret_cast<const float4*>(&g_xh[(size_t)s4.w * 64 + xofs]));
        float w0 = __expf(lrelu(g_es1[s4.x * 4 + myh] + ed_l) - M);
        float w1 = __expf(lrelu(g_es1[s4.y * 4 + myh] + ed_l) - M);
        float w2 = __expf(lrelu(g_es1[s4.z * 4 + myh] + ed_l) - M);
        float w3 = __expf(lrelu(g_es1[s4.w * 4 + myh] + ed_l) - M);
        ss += (w0 + w1) + (w2 + w3);
        const __half2* h0 = reinterpret_cast<const __half2*>(&r0);
        const __half2* h1 = reinterpret_cast<const __half2*>(&r1);
        const __half2* h2 = reinterpret_cast<const __half2*>(&r2);
        const __half2* h3 = reinterpret_cast<const __half2*>(&r3);
#pragma unroll
        for (int q = 0; q < 4; q++) {
            float2 f0 = __half22float2(h0[q]);
            float2 f1 = __half22float2(h1[q]);
            float2 f2 = __half22float2(h2[q]);
            float2 f3 = __half22float2(h3[q]);
            acc[2 * q]     = fmaf(w0, f0.x, fmaf(w1, f1.x, fmaf(w2, f2.x, fmaf(w3, f3.x, acc[2 * q]))));
            acc[2 * q + 1] = fmaf(w0, f0.y, fmaf(w1, f1.y, fmaf(w2, f2.y, fmaf(w3, f3.y, acc[2 * q + 1]))));
        }
    }
    for (; j < end; j++) AGG1_ONE(g_csr_src[j]);
#undef AGG1_ONE

    float inv = 1.f / (ss + 1e-8f);
    union { uint4 u; __half2 h2[4]; } pk;
#pragma unroll
    for (int q = 0; q < 4; q++)
        pk.h2[q] = __floats2half2_rn(acc[2 * q] * inv, acc[2 * q + 1] * inv);
    __stcs(reinterpret_cast<uint4*>(&g_xagg[(size_t)d * 256 + lane * 8]), pk.u);
}

// ---------------- fused GEMM1b+GEMM2: h2 = elu(xagg@blockdiagW1)@W2, + es2/ed2 -----
__global__ void __launch_bounds__(256) k_gemm12_mma(const float* __restrict__ a2) {
    extern __shared__ __half sm[];
    __half* Bt1 = sm;                       // [256][72]
    __half* Bt2 = Bt1 + 256 * 72;           // [64][264]
    __half* As  = Bt2 + 64 * 264;           // [32][264]
    __half* O   = As + 32 * 264;            // [32][264]
    float* part_es = reinterpret_cast<float*>(O + 32 * 264);  // [4][32]
    float* part_ed = part_es + 128;

    int t = threadIdx.x;
    int lane = t & 31, wid = t >> 5;
    int g = lane >> 2, tg = lane & 3;

#pragma unroll
    for (int i = 0; i < 8; i++) {
        int u = t + i * 256;
        int r = u >> 3, c = (u & 7) * 8;
        *reinterpret_cast<uint4*>(&Bt1[r * 72 + c]) =
            *reinterpret_cast<const uint4*>(&g_w1t[r * 64 + c]);
    }
#pragma unroll
    for (int i = 0; i < 8; i++) {
        int u = t + i * 256;
        int r = u >> 5, c = (u & 31) * 8;
        *reinterpret_cast<uint4*>(&Bt2[r * 264 + c]) =
            *reinterpret_cast<const uint4*>(&g_w2t[r * 256 + c]);
    }

    int wm = (wid & 1) * 16;
    int wn1 = (wid >> 1) * 64;
    int akofs = (wid >> 1) * 64;
    int wn2 = (wid >> 1) * 16;
    float a2l2[2][2], a2r2[2][2];
#pragma unroll
    for (int ns = 0; ns < 2; ns++)
#pragma unroll
        for (int c = 0; c < 2; c++) {
            int col = wn2 + ns * 8 + 2 * tg + c;
            a2l2[ns][c] = a2[col];
            a2r2[ns][c] = a2[64 + col];
        }

    float mx_es = -3.4e38f, mx_ed = -3.4e38f;
    const int NT = NN_PAD / 32;
    for (int tile = blockIdx.x; tile < NT; tile += gridDim.x) {
        __syncthreads();
#pragma unroll
        for (int i = 0; i < 4; i++) {
            int u = t + i * 256;
            int r = u >> 5, c = (u & 31) * 8;
            *reinterpret_cast<uint4*>(&As[r * 264 + c]) =
                *reinterpret_cast<const uint4*>(&g_xagg[(size_t)(tile * 32 + r) * 256 + c]);
        }
        __syncthreads();

        float acc[8][4];
#pragma unroll
        for (int ns = 0; ns < 8; ns++)
#pragma unroll
            for (int q = 0; q < 4; q++) acc[ns][q] = 0.f;
#pragma unroll
        for (int kt = 0; kt < 4; kt++) {
            int kbA = akofs + kt * 16 + 2 * tg;
            int kbB = kt * 16 + 2 * tg;
            unsigned a0 = lds_u32(&As[(wm + g) * 264 + kbA]);
            unsigned a1f = lds_u32(&As[(wm + g + 8) * 264 + kbA]);
            unsigned a2f = lds_u32(&As[(wm + g) * 264 + kbA + 8]);
            unsigned a3f = lds_u32(&As[(wm + g + 8) * 264 + kbA + 8]);
#pragma unroll
            for (int ns = 0; ns < 8; ns++) {
                unsigned b0 = lds_u32(&Bt1[(wn1 + ns * 8 + g) * 72 + kbB]);
                unsigned b1 = lds_u32(&Bt1[(wn1 + ns * 8 + g) * 72 + kbB + 8]);
                mma16816(acc[ns][0], acc[ns][1], acc[ns][2], acc[ns][3],
                         a0, a1f, a2f, a3f, b0, b1);
            }
        }
#pragma unroll
        for (int ns = 0; ns < 8; ns++) {
            int col = wn1 + ns * 8 + 2 * tg;
#pragma unroll
            for (int q = 0; q < 4; q++)
                acc[ns][q] = (acc[ns][q] > 0.f) ? acc[ns][q] : expm1f(acc[ns][q]);
            *reinterpret_cast<__half2*>(&O[(wm + g) * 264 + col]) =
                __floats2half2_rn(acc[ns][0], acc[ns][1]);
            *reinterpret_cast<__half2*>(&O[(wm + g + 8) * 264 + col]) =
                __floats2half2_rn(acc[ns][2], acc[ns][3]);
        }
        __syncthreads();

        float acc2[2][4];
#pragma unroll
        for (int ns = 0; ns < 2; ns++)
#pragma unroll
            for (int q = 0; q < 4; q++) acc2[ns][q] = 0.f;
#pragma unroll
        for (int kt = 0; kt < 16; kt++) {
            int kb = kt * 16 + 2 * tg;
            unsigned a0 = lds_u32(&O[(wm + g) * 264 + kb]);
            unsigned a1f = lds_u32(&O[(wm + g + 8) * 264 + kb]);
            unsigned a2f = lds_u32(&O[(wm + g) * 264 + kb + 8]);
            unsigned a3f = lds_u32(&O[(wm + g + 8) * 264 + kb + 8]);
#pragma unroll
            for (int ns = 0; ns < 2; ns++) {
                unsigned b0 = lds_u32(&Bt2[(wn2 + ns * 8 + g) * 264 + kb]);
                unsigned b1 = lds_u32(&Bt2[(wn2 + ns * 8 + g) * 264 + kb + 8]);
                mma16816(acc2[ns][0], acc2[ns][1], acc2[ns][2], acc2[ns][3],
                         a0, a1f, a2f, a3f, b0, b1);
            }
        }
        int row0 = tile * 32 + wm + g;
#pragma unroll
        for (int ns = 0; ns < 2; ns++) {
            int col = wn2 + ns * 8 + 2 * tg;
            if (row0 < NN)
                *reinterpret_cast<__half2*>(&g_h2h[(size_t)row0 * 64 + col]) =
                    __floats2half2_rn(acc2[ns][0], acc2[ns][1]);
            if (row0 + 8 < NN)
                *reinterpret_cast<__half2*>(&g_h2h[(size_t)(row0 + 8) * 64 + col]) =
                    __floats2half2_rn(acc2[ns][2], acc2[ns][3]);
        }
        float es0 = 0.f, ed0 = 0.f, es8 = 0.f, ed8 = 0.f;
#pragma unroll
        for (int ns = 0; ns < 2; ns++) {
            es0 = fmaf(acc2[ns][0], a2l2[ns][0], fmaf(acc2[ns][1], a2l2[ns][1], es0));
            ed0 = fmaf(acc2[ns][0], a2r2[ns][0], fmaf(acc2[ns][1], a2r2[ns][1], ed0));
            es8 = fmaf(acc2[ns][2], a2l2[ns][0], fmaf(acc2[ns][3], a2l2[ns][1], es8));
            ed8 = fmaf(acc2[ns][2], a2r2[ns][0], fmaf(acc2[ns][3], a2r2[ns][1], ed8));
        }
#pragma unroll
        for (int o = 1; o < 4; o <<= 1) {
            es0 += __shfl_xor_sync(0xffffffffu, es0, o);
            ed0 += __shfl_xor_sync(0xffffffffu, ed0, o);
            es8 += __shfl_xor_sync(0xffffffffu, es8, o);
            ed8 += __shfl_xor_sync(0xffffffffu, ed8, o);
        }
        if (tg == 0) {
            int cg = wid >> 1;
            part_es[cg * 32 + wm + g] = es0;
            part_es[cg * 32 + wm + g + 8] = es8;
            part_ed[cg * 32 + wm + g] = ed0;
            part_ed[cg * 32 + wm + g + 8] = ed8;
        }
        __syncthreads();
        if (t < 32) {
            int row = tile * 32 + t;
            float es = part_es[t] + part_es[32 + t] + part_es[64 + t] + part_es[96 + t];
            float ed = part_ed[t] + part_ed[32 + t] + part_ed[64 + t] + part_ed[96 + t];
            if (row < NN) {
                g_es2[row] = es;
                g_ed2[row] = ed;
                mx_es = fmaxf(mx_es, es);
                mx_ed = fmaxf(mx_ed, ed);
            }
        }
    }
    if (t < 32 && mx_es > -3.3e38f) {
        atomicMax(&g_maxes2_u, enc_f(mx_es));
        atomicMax(&g_maxed2_u, enc_f(mx_ed));
    }
}

// ---------------- layer-2 aggregation: warp/dst, demand-pruned ---------------------
__global__ void __launch_bounds__(256) k_agg2(
    const float* __restrict__ user, const float* __restrict__ item) {
    int gw = (blockIdx.x * 256 + threadIdx.x) >> 5;
    int lane = threadIdx.x & 31;
    if (gw >= NN) return;
    int d = gw;
    if (!g_need[d]) return;
    int n0 = g_off[d];
    int cnt = g_cnt[d];
    float M = lrelu(dec_f(g_maxes2_u) + dec_f(g_maxed2_u));
    float2 acc = make_float2(0.f, 0.f);
    float ss = 0.f;
    float ed_d = g_ed2[d];
    int j = n0, end = n0 + cnt;
    for (; j + 3 < end; j += 4) {
        int s0 = g_csr_src[j], s1 = g_csr_src[j + 1];
        int s2 = g_csr_src[j + 2], s3 = g_csr_src[j + 3];
        __half2 hr0 = __ldcg(reinterpret_cast<const __half2*>(&g_h2h[(size_t)s0 * 64 + lane * 2]));
        __half2 hr1 = __ldcg(reinterpret_cast<const __half2*>(&g_h2h[(size_t)s1 * 64 + lane * 2]));
        __half2 hr2 = __ldcg(reinterpret_cast<const __half2*>(&g_h2h[(size_t)s2 * 64 + lane * 2]));
        __half2 hr3 = __ldcg(reinterpret_cast<const __half2*>(&g_h2h[(size_t)s3 * 64 + lane * 2]));
        float w0 = __expf(lrelu(g_es2[s0] + ed_d) - M);
        float w1 = __expf(lrelu(g_es2[s1] + ed_d) - M);
        float w2 = __expf(lrelu(g_es2[s2] + ed_d) - M);
        float w3 = __expf(lrelu(g_es2[s3] + ed_d) - M);
        ss += (w0 + w1) + (w2 + w3);
        float2 f0 = __half22float2(hr0);
        float2 f1 = __half22float2(hr1);
        float2 f2 = __half22float2(hr2);
        float2 f3 = __half22float2(hr3);
        acc.x = fmaf(w0, f0.x, fmaf(w1, f1.x, fmaf(w2, f2.x, fmaf(w3, f3.x, acc.x))));
        acc.y = fmaf(w0, f0.y, fmaf(w1, f1.y, fmaf(w2, f2.y, fmaf(w3, f3.y, acc.y))));
    }
    for (; j < end; j++) {
        int s0 = g_csr_src[j];
        __half2 hr0 = __ldcg(reinterpret_cast<const __half2*>(&g_h2h[(size_t)s0 * 64 + lane * 2]));
        float w0 = __expf(lrelu(g_es2[s0] + ed_d) - M);
        ss += w0;
        float2 f0 = __half22float2(hr0);
        acc.x = fmaf(w0, f0.x, acc.x);
        acc.y = fmaf(w0, f0.y, acc.y);
    }
    float inv = 1.f / (ss + 1e-8f);
    float2 emb = (d < NUSERS)
        ? *reinterpret_cast<const float2*>(&user[(size_t)d * 64 + lane * 2])
        : *reinterpret_cast<const float2*>(&item[(size_t)(d - NUSERS) * 64 + lane * 2]);
    float2 out = make_float2(acc.x * inv + emb.x, acc.y * inv + emb.y);
    *reinterpret_cast<float2*>(&g_out2[(size_t)d * 64 + lane * 2]) = out;
}

// ---------------- final scoring + state reset for next call ------------------------
__global__ void k_final(const int* __restrict__ uid, const int* __restrict__ iid,
                        float* __restrict__ out) {
    int tid = blockIdx.x * blockDim.x + threadIdx.x;
    if (tid < NN) { g_cnt[tid] = 0; g_need[tid] = 0; }
    if (tid == 0) {
        g_maxes1_u = 0x007FFFFFu; g_maxed1_u = 0x007FFFFFu;
        g_maxes2_u = 0x007FFFFFu; g_maxed2_u = 0x007FFFFFu;
    }
    int gw = tid >> 5;
    int lane = threadIdx.x & 31;
    if (gw >= NB) return;
    int u = uid[gw];
    int it = NUSERS + iid[gw];
    float p = 0.f;
#pragma unroll
    for (int i = 0; i < 2; i++) {
        int f = i * 32 + lane;
        p += g_out2[(size_t)u * 64 + f] * g_out2[(size_t)it * 64 + f];
    }
#pragma unroll
    for (int o = 16; o > 0; o >>= 1) p += __shfl_down_sync(0xffffffffu, p, o);
    if (lane == 0) out[gw] = p;
}

// ---------------- launch -------------------------------------------------------------
#define GEMM12_SMEM (256*72*2 + 64*264*2 + 32*264*2 + 32*264*2 + 256*4)

extern "C" void kernel_launch(void* const* d_in, const int* in_sizes, int n_in,
                              void* d_out, int out_size) {
    const float* user = (const float*)d_in[0];
    const float* item = (const float*)d_in[1];
    const float* W1 = (const float*)d_in[2];
    const float* a1 = (const float*)d_in[3];
    const float* W2 = (const float*)d_in[4];
    const float* a2 = (const float*)d_in[5];
    const int* ei = (const int*)d_in[6];
    const int* uid = (const int*)d_in[7];
    const int* iid = (const int*)d_in[8];
    float* out = (float*)d_out;

    static cudaStream_t s2 = nullptr;
    static cudaEvent_t evFork = nullptr, evJoin = nullptr;
    if (s2 == nullptr) {
        cudaStreamCreateWithFlags(&s2, cudaStreamNonBlocking);
        cudaEventCreateWithFlags(&evFork, cudaEventDisableTiming);
        cudaEventCreateWithFlags(&evJoin, cudaEventDisableTiming);
        cudaFuncSetAttribute(k_gemm12_mma,
                             cudaFuncAttributeMaxDynamicSharedMemorySize, GEMM12_SMEM);
    }

    // fork: chain B (CSR build) on s2
    cudaEventRecord(evFork, 0);
    cudaStreamWaitEvent(s2, evFork, 0);
    k_hist<<<2048, 256, 0, s2>>>(ei);
    k_scan_block<<<NBLK_SCAN, 1024, 0, s2>>>();
    k_scan_fin<<<NBLK_SCAN, 1024, 0, s2>>>();
    k_scatter<<<(NE + 255) / 256, 256, 0, s2>>>(ei);
    cudaEventRecord(evJoin, s2);

    // chain A: w1a prep + demand marks (one kernel), then fused convert + es1/ed1
    k_prep_mark<<<1 + (NB + 255) / 256, 256>>>(W1, a1, uid, iid);
    k_cvt_fused<<<2048, 256>>>(user, item, W1, W2);

    // join, then serial tail
    cudaStreamWaitEvent(0, evJoin, 0);
    k_agg1<<<(NN * 32 + 255) / 256, 256>>>();
    k_gemm12_mma<<<296, 256, GEMM12_SMEM>>>(a2);
    k_agg2<<<(NN * 32 + 255) / 256, 256>>>(user, item);
    k_final<<<NB * 32 / 256, 256>>>(uid, iid, out);
}